// round 16
// baseline (speedup 1.0000x reference)
#include <cuda_runtime.h>
#include <cuda_fp16.h>

#define NMAX 4096
#define SMAX 32
#define DDIM 128
#define CAP  4500000u
#define VLD  4224
#define EPSK 1e-6f
#define ITS  20
#define FNB  128

// ---------------- static device scratch (allocation-free) ----------------
__device__ float  g_Xt[(size_t)SMAX*NMAX*DDIM];
__device__ float  g_Xc[(size_t)SMAX*NMAX*DDIM];
__device__ float  g_nrmT[SMAX*NMAX];
__device__ float  g_nrmC[SMAX*NMAX];
__device__ __half g_Km[(size_t)SMAX*CAP];          // 288MB K (fp16)
__device__ __half g_Mh[(size_t)SMAX*CAP];          // 288MB M (fp16)
__device__ float  g_y[SMAX*VLD];
__device__ float  g_z[SMAX*VLD];                   // holds u
__device__ float  g_ypart[(size_t)SMAX*4*VLD];     // per-quarter y partials
__device__ int    g_it[NMAX], g_ic[NMAX];
__device__ int    g_nt, g_nc, g_ld;
__device__ float  g_a0, g_an, g_b0, g_bn;
__device__ float  g_psum[SMAX*1024];
__device__ float  g_pmax[SMAX*1024];
__device__ float  g_sumv[SMAX], g_maxv[SMAX];
__device__ float  g_cpart[SMAX*129];
__device__ unsigned g_barcnt, g_bargen;

// ---------------- grid-wide barrier (FNB blocks resident) ----------------
__device__ __forceinline__ void grid_sync() {
    __syncthreads();
    if (threadIdx.x == 0) {
        __threadfence();
        unsigned gen = atomicAdd(&g_bargen, 0u);
        if (atomicAdd(&g_barcnt, 1u) == FNB - 1) {
            atomicExch(&g_barcnt, 0u);
            __threadfence();
            atomicAdd(&g_bargen, 1u);
        } else {
            while (atomicAdd(&g_bargen, 0u) == gen) {}
        }
        __threadfence();
    }
    __syncthreads();
}

__device__ __forceinline__ unsigned f2tf32(float x) {
    unsigned u;
    asm("cvt.rna.tf32.f32 %0, %1;" : "=r"(u) : "f"(x));
    return u;
}

// ---------------- partition: scan t, index lists + scalars ----------------
__global__ void partition_k(const int* __restrict__ t) {
    __shared__ int cnt[256];
    const int tid = threadIdx.x;
    const int base = tid * 16;
    int c = 0;
    #pragma unroll
    for (int k = 0; k < 16; k++) c += (t[base + k] > 0);
    cnt[tid] = c;
    __syncthreads();
    for (int off = 1; off < 256; off <<= 1) {
        int v = (tid >= off) ? cnt[tid - off] : 0;
        __syncthreads();
        cnt[tid] += v;
        __syncthreads();
    }
    const int nt = cnt[255];
    int tp = cnt[tid] - c;
    for (int k = 0; k < 16; k++) {
        int idx = base + k;
        if (t[idx] > 0) { g_it[tp] = idx; tp++; }
        else            { g_ic[idx - tp] = idx; }
    }
    if (!tid) {
        int nc = NMAX - nt;
        g_nt = nt; g_nc = nc;
        g_ld = ((nc + 1 + 63) >> 6) << 6;
        float p = (float)nt / (float)NMAX;
        g_a0 = p / (float)nt;       g_an = 1.0f - p;
        g_b0 = (1.0f - p) / (float)nc; g_bn = p;
    }
}

// ---------------- gather rows ----------------
__global__ void gather_k(const float* __restrict__ X) {
    size_t idx = (size_t)blockIdx.x * 256 + threadIdx.x;
    int d = (int)(idx & 127);
    int r = (int)((idx >> 7) & 4095);
    int s = (int)(idx >> 19);
    if (r < g_nt) g_Xt[idx] = X[(((size_t)g_it[r]) * SMAX + s) * DDIM + d];
    if (r < g_nc) g_Xc[idx] = X[(((size_t)g_ic[r]) * SMAX + s) * DDIM + d];
}

// ---------------- squared row norms ----------------
__global__ void norms_k() {
    const int gidx = blockIdx.x * 8 + (threadIdx.x >> 5);
    const int lane = threadIdx.x & 31;
    const int s = gidx >> 12, r = gidx & 4095;
    if (r < g_nt) {
        float4 v = *(const float4*)(g_Xt + ((size_t)s * NMAX + r) * DDIM + lane * 4);
        float sq = v.x*v.x + v.y*v.y + v.z*v.z + v.w*v.w;
        #pragma unroll
        for (int o = 16; o; o >>= 1) sq += __shfl_down_sync(~0u, sq, o);
        if (!lane) g_nrmT[s * NMAX + r] = sq;
    }
    if (r < g_nc) {
        float4 v = *(const float4*)(g_Xc + ((size_t)s * NMAX + r) * DDIM + lane * 4);
        float sq = v.x*v.x + v.y*v.y + v.z*v.z + v.w*v.w;
        #pragma unroll
        for (int o = 16; o; o >>= 1) sq += __shfl_down_sync(~0u, sq, o);
        if (!lane) g_nrmC[s * NMAX + r] = sq;
    }
}

// ------- TF32 tensor-core GEMM: M = nrT + nrC - 2 Xt Xc^T (fp16 out) --------
__global__ __launch_bounds__(256) void gemm_k() {
    const int nt = g_nt, nc = g_nc, ld = g_ld;
    const int by = blockIdx.y, bx = blockIdx.x, gz = blockIdx.z;
    const int s = gz;
    const int tid = threadIdx.x;
    if (by * 128 >= nt || bx * 128 >= nc) {
        if (!tid) { g_psum[s*1024 + by*32 + bx] = 0.f; g_pmax[s*1024 + by*32 + bx] = 0.f; }
        return;
    }
    const float* A = g_Xt + ((size_t)s * NMAX + by * 128) * DDIM;
    const float* B = g_Xc + ((size_t)s * NMAX + bx * 128) * DDIM;
    __shared__ unsigned As[128][36];
    __shared__ unsigned Bs[128][36];
    const int warp = tid >> 5, lane = tid & 31;
    const int wm = (warp >> 2) * 64, wn = (warp & 3) * 32;
    const int qr = lane >> 2, qc = lane & 3;

    float c[4][4][4];
    #pragma unroll
    for (int mt = 0; mt < 4; mt++)
        #pragma unroll
        for (int nn = 0; nn < 4; nn++)
            #pragma unroll
            for (int e = 0; e < 4; e++) c[mt][nn][e] = 0.f;

    for (int k0 = 0; k0 < DDIM; k0 += 32) {
        __syncthreads();
        #pragma unroll
        for (int l = 0; l < 4; l++) {
            int idx = l * 256 + tid;
            int row = idx >> 3, kq = idx & 7;
            float4 va = *(const float4*)(A + (size_t)row * DDIM + k0 + kq * 4);
            uint4 ua = make_uint4(f2tf32(va.x), f2tf32(va.y), f2tf32(va.z), f2tf32(va.w));
            *(uint4*)&As[row][kq * 4] = ua;
            float4 vb = *(const float4*)(B + (size_t)row * DDIM + k0 + kq * 4);
            uint4 ub = make_uint4(f2tf32(vb.x), f2tf32(vb.y), f2tf32(vb.z), f2tf32(vb.w));
            *(uint4*)&Bs[row][kq * 4] = ub;
        }
        __syncthreads();
        #pragma unroll
        for (int ks = 0; ks < 4; ks++) {
            const int kb = ks * 8 + qc;
            unsigned af[4][4], bf[4][2];
            #pragma unroll
            for (int mt = 0; mt < 4; mt++) {
                int row = wm + mt * 16 + qr;
                af[mt][0] = As[row][kb];
                af[mt][1] = As[row + 8][kb];
                af[mt][2] = As[row][kb + 4];
                af[mt][3] = As[row + 8][kb + 4];
            }
            #pragma unroll
            for (int nn = 0; nn < 4; nn++) {
                int col = wn + nn * 8 + qr;
                bf[nn][0] = Bs[col][kb];
                bf[nn][1] = Bs[col][kb + 4];
            }
            #pragma unroll
            for (int mt = 0; mt < 4; mt++)
                #pragma unroll
                for (int nn = 0; nn < 4; nn++) {
                    asm volatile(
                        "mma.sync.aligned.m16n8k8.row.col.f32.tf32.tf32.f32 "
                        "{%0,%1,%2,%3}, {%4,%5,%6,%7}, {%8,%9}, {%0,%1,%2,%3};\n"
                        : "+f"(c[mt][nn][0]), "+f"(c[mt][nn][1]),
                          "+f"(c[mt][nn][2]), "+f"(c[mt][nn][3])
                        : "r"(af[mt][0]), "r"(af[mt][1]), "r"(af[mt][2]), "r"(af[mt][3]),
                          "r"(bf[nn][0]), "r"(bf[nn][1]));
                }
        }
    }

    __half* Mp = g_Mh + (size_t)gz * CAP;
    float lmax = 0.f, lsum = 0.f;
    #pragma unroll
    for (int mt = 0; mt < 4; mt++) {
        float nrh[2];
        #pragma unroll
        for (int h = 0; h < 2; h++) {
            int gr = by * 128 + wm + mt * 16 + qr + h * 8;
            nrh[h] = (gr < nt) ? g_nrmT[s * NMAX + gr] : 0.f;
        }
        #pragma unroll
        for (int nn = 0; nn < 4; nn++) {
            int gc = bx * 128 + wn + nn * 8 + 2 * qc;
            float nc0 = (gc     < nc) ? g_nrmC[s * NMAX + gc]     : 0.f;
            float nc1 = (gc + 1 < nc) ? g_nrmC[s * NMAX + gc + 1] : 0.f;
            #pragma unroll
            for (int h = 0; h < 2; h++) {
                int gr = by * 128 + wm + mt * 16 + qr + h * 8;
                if (gr >= nt) continue;
                float m0 = fmaf(-2.f, c[mt][nn][h * 2 + 0], nrh[h] + nc0);
                float m1 = fmaf(-2.f, c[mt][nn][h * 2 + 1], nrh[h] + nc1);
                if (gc + 1 < nc) {
                    *(__half2*)(Mp + (size_t)gr * ld + gc) = __floats2half2_rn(m0, m1);
                    lmax = fmaxf(lmax, fmaxf(m0, m1));
                    lsum += m0 + m1;
                } else if (gc < nc) {
                    Mp[(size_t)gr * ld + gc] = __float2half(m0);
                    lmax = fmaxf(lmax, m0);
                    lsum += m0;
                }
            }
        }
    }
    #pragma unroll
    for (int o = 16; o; o >>= 1) {
        lmax = fmaxf(lmax, __shfl_down_sync(~0u, lmax, o));
        lsum += __shfl_down_sync(~0u, lsum, o);
    }
    __shared__ float rmx[8], rsm[8];
    if (!lane) { rmx[warp] = lmax; rsm[warp] = lsum; }
    __syncthreads();
    if (!tid) {
        float mx = rmx[0], sm = rsm[0];
        #pragma unroll
        for (int w = 1; w < 8; w++) { mx = fmaxf(mx, rmx[w]); sm += rsm[w]; }
        g_pmax[s*1024 + by*32 + bx] = mx;
        g_psum[s*1024 + by*32 + bx] = sm;
    }
}

// ---------------- deterministic reduce of per-block partials ----------------
__global__ void reduce_k() {
    const int s = blockIdx.x, tid = threadIdx.x;
    __shared__ float ss[256], sm[256];
    float a = 0.f, m = 0.f;
    for (int k = tid; k < 1024; k += 256) { a += g_psum[s*1024 + k]; m = fmaxf(m, g_pmax[s*1024 + k]); }
    ss[tid] = a; sm[tid] = m;
    __syncthreads();
    for (int o = 128; o; o >>= 1) {
        if (tid < o) { ss[tid] += ss[tid + o]; sm[tid] = fmaxf(sm[tid], sm[tid + o]); }
        __syncthreads();
    }
    if (!tid) { g_sumv[s] = ss[0]; g_maxv[s] = sm[0]; }
}

// -------- build K = exp(-el*Mt)+eps (fp16), augment M, seed u0 = a ----------
__global__ void kbuild_k() {
    const int nt = g_nt, nc = g_nc, ld = g_ld;
    const int i = blockIdx.x;
    if (i > nt) return;
    const int g = blockIdx.y, s = g, tid = threadIdx.x;
    const float delta = g_maxv[s];
    const float el = ((float)nt * (float)nc) / g_sumv[s];
    const float Kd = __expf(-el * delta) + EPSK;
    __half* Kp = g_Km + (size_t)g * CAP + (size_t)i * ld;
    __half* Mp = g_Mh + (size_t)g * CAP + (size_t)i * ld;
    if (i < nt) {
        for (int j = tid; j < ld; j += 256) {
            float kv;
            if (j < nc)       kv = __expf(-el * __half2float(Mp[j])) + EPSK;
            else if (j == nc) { kv = Kd; Mp[j] = __float2half(delta); }
            else              kv = 0.f;
            Kp[j] = __float2half(kv);
        }
    } else {
        for (int j = tid; j < ld; j += 256) {
            float kv;
            if (j < nc)       { kv = Kd; Mp[j] = __float2half(delta); }
            else if (j == nc) { kv = 1.0f + EPSK; Mp[j] = __float2half(0.f); }
            else              kv = 0.f;
            Kp[j] = __float2half(kv);
        }
    }
    if (!tid) g_z[g * VLD + i] = (i < nt) ? g_a0 : g_an;   // u0 = a
}

// ---------------- bootstrap A: y = K^T u0 ----------------
__global__ __launch_bounds__(256) void spmvA_k() {
    const int nt = g_nt, nc = g_nc, ld = g_ld;
    const int j0 = blockIdx.x * 128;
    if (j0 > nc) return;
    const int g = blockIdx.y, tid = threadIdx.x;
    __shared__ float us[NMAX + 1];
    __shared__ float red[16 * 128];
    const float* zp = g_z + g * VLD;
    for (int i = tid; i <= nt; i += 256) us[i] = zp[i];
    __syncthreads();
    const int cg = tid & 15, ph = tid >> 4;
    const __half* Kp = g_Km + (size_t)g * CAP + j0 + cg * 8;
    float acc[8];
    #pragma unroll
    for (int k = 0; k < 8; k++) acc[k] = 0.f;
    #pragma unroll 4
    for (int i = ph; i <= nt; i += 16) {
        uint4 kv = *(const uint4*)(Kp + (size_t)i * ld);
        float u = us[i];
        const __half2* h = (const __half2*)&kv;
        float2 f;
        f = __half22float2(h[0]); acc[0] = fmaf(f.x, u, acc[0]); acc[1] = fmaf(f.y, u, acc[1]);
        f = __half22float2(h[1]); acc[2] = fmaf(f.x, u, acc[2]); acc[3] = fmaf(f.y, u, acc[3]);
        f = __half22float2(h[2]); acc[4] = fmaf(f.x, u, acc[4]); acc[5] = fmaf(f.y, u, acc[5]);
        f = __half22float2(h[3]); acc[6] = fmaf(f.x, u, acc[6]); acc[7] = fmaf(f.y, u, acc[7]);
    }
    #pragma unroll
    for (int k = 0; k < 8; k++) red[ph * 128 + cg * 8 + k] = acc[k];
    __syncthreads();
    if (tid < 128) {
        float y = 0.f;
        #pragma unroll
        for (int p = 0; p < 16; p++) y += red[p * 128 + tid];
        int j = j0 + tid;
        if (j <= nc) g_y[g * VLD + j] = y;
    }
}

// ------ fused persistent Sinkhorn: per iteration ONE pass over K ----------
// z_i = K_i . w  (w = b/y);  u_i = a_i/z_i;  yacc_j += u_i K_ij  (next y)
__global__ __launch_bounds__(1024, 1) void fused_k() {
    const int nt = g_nt, nc = g_nc, ld = g_ld;
    const int bid = blockIdx.x, tid = threadIdx.x;
    const int g = bid >> 2, q = bid & 3;
    __shared__ __align__(16) float ws[VLD];
    __shared__ __align__(16) float yacc[VLD];
    __shared__ float u_g[8];
    __shared__ float dotred[8][4];
    const float a0 = g_a0, an = g_an, b0 = g_b0, bn = g_bn;
    const int nrows = nt + 1;
    const int qsz = (nrows + 3) >> 2;
    const int r0 = q * qsz;
    const int rend = min(r0 + qsz, nrows);
    const int group = tid >> 7;          // 0..7 (row within wave)
    const int l128 = tid & 127;
    const int w4 = (tid >> 5) & 3;       // warp within group
    const int lane = tid & 31;
    const int nch = ld >> 3;             // uint4 chunks per row
    const int nj4 = ld >> 2;             // float4 col groups
    const __half* Kg = g_Km + (size_t)g * CAP;
    const int nw = (rend > r0) ? ((rend - r0 + 7) >> 3) : 0;

    for (int it = 0; it < ITS; ++it) {
        const float* yp = g_y + g * VLD;
        for (int j = tid; j < VLD; j += 1024) {
            float w = 0.f;
            if (j <= nc) w = ((j < nc) ? b0 : bn) / yp[j];
            ws[j] = w;
            yacc[j] = 0.f;
        }
        __syncthreads();

        int prev_base = -1;
        for (int w = 0; w < nw; ++w) {
            const int rbase = r0 + w * 8;
            const int row = rbase + group;
            // 1) accumulate previous wave into yacc (K rows hot in L1)
            if (prev_base >= 0) {
                for (int jc = tid; jc < nj4; jc += 1024) {
                    float4 y4 = *(float4*)&yacc[jc * 4];
                    #pragma unroll
                    for (int r = 0; r < 8; r++) {
                        float ur = u_g[r];
                        if (ur != 0.f) {
                            const __half2* kp = (const __half2*)(Kg + (size_t)(prev_base + r) * ld + jc * 4);
                            float2 f0 = __half22float2(kp[0]);
                            float2 f1 = __half22float2(kp[1]);
                            y4.x = fmaf(ur, f0.x, y4.x); y4.y = fmaf(ur, f0.y, y4.y);
                            y4.z = fmaf(ur, f1.x, y4.z); y4.w = fmaf(ur, f1.y, y4.w);
                        }
                    }
                    *(float4*)&yacc[jc * 4] = y4;
                }
            }
            // 2) dot for current wave
            float acc = 0.f;
            const bool active = (row < rend);
            if (active) {
                const __half* Kr = Kg + (size_t)row * ld;
                for (int c = l128; c < nch; c += 128) {
                    uint4 kv = *(const uint4*)(Kr + c * 8);
                    float4 w0 = *(const float4*)&ws[c * 8];
                    float4 w1 = *(const float4*)&ws[c * 8 + 4];
                    const __half2* h = (const __half2*)&kv;
                    float2 f;
                    f = __half22float2(h[0]); acc = fmaf(f.x, w0.x, acc); acc = fmaf(f.y, w0.y, acc);
                    f = __half22float2(h[1]); acc = fmaf(f.x, w0.z, acc); acc = fmaf(f.y, w0.w, acc);
                    f = __half22float2(h[2]); acc = fmaf(f.x, w1.x, acc); acc = fmaf(f.y, w1.y, acc);
                    f = __half22float2(h[3]); acc = fmaf(f.x, w1.z, acc); acc = fmaf(f.y, w1.w, acc);
                }
            }
            #pragma unroll
            for (int o = 16; o; o >>= 1) acc += __shfl_down_sync(~0u, acc, o);
            if (!lane) dotred[group][w4] = acc;
            __syncthreads();                     // dotred ready; accumulate done
            if (l128 == 0) {
                float z = (dotred[group][0] + dotred[group][1]) +
                          (dotred[group][2] + dotred[group][3]);
                float u = 0.f;
                if (active) { u = ((row < nt) ? a0 : an) / z; g_z[g * VLD + row] = u; }
                u_g[group] = u;
            }
            prev_base = rbase;
            __syncthreads();                     // u_g ready for next accumulate
        }
        // epilogue: accumulate last wave
        if (prev_base >= 0) {
            for (int jc = tid; jc < nj4; jc += 1024) {
                float4 y4 = *(float4*)&yacc[jc * 4];
                #pragma unroll
                for (int r = 0; r < 8; r++) {
                    float ur = u_g[r];
                    if (ur != 0.f) {
                        const __half2* kp = (const __half2*)(Kg + (size_t)(prev_base + r) * ld + jc * 4);
                        float2 f0 = __half22float2(kp[0]);
                        float2 f1 = __half22float2(kp[1]);
                        y4.x = fmaf(ur, f0.x, y4.x); y4.y = fmaf(ur, f0.y, y4.y);
                        y4.z = fmaf(ur, f1.x, y4.z); y4.w = fmaf(ur, f1.y, y4.w);
                    }
                }
                *(float4*)&yacc[jc * 4] = y4;
            }
        }
        __syncthreads();
        // write this quarter's partial y
        float* pp = g_ypart + ((size_t)g * 4 + q) * VLD;
        for (int j = tid; j < VLD; j += 1024) pp[j] = yacc[j];
        grid_sync();
        // deterministic reduce of 4 partials -> g_y (blocks 0..31)
        if (bid < SMAX) {
            const float* p0 = g_ypart + (size_t)bid * 4 * VLD;
            for (int j = tid; j < VLD; j += 1024)
                g_y[bid * VLD + j] = (p0[j] + p0[VLD + j]) + (p0[2 * VLD + j] + p0[3 * VLD + j]);
        }
        grid_sync();
    }
}

// ---------------- partial = sum_ij u_i v_j K_ij Mt_ij ----------------
__global__ __launch_bounds__(256) void contract_k() {
    const int nt = g_nt, nc = g_nc, ld = g_ld;
    const int bx = blockIdx.x, g = blockIdx.y;
    const int s = g, tid = threadIdx.x;
    const int i0 = bx * 32;
    if (i0 > nt) { if (!tid) g_cpart[s * 129 + bx] = 0.f; return; }
    __shared__ __align__(16) float ws[VLD];
    __shared__ float wp[8];
    const float b0 = g_b0, bn = g_bn;
    const float* yp = g_y + g * VLD;
    for (int j = tid; j < ld; j += 256) {
        float w = 0.f;
        if (j <= nc) w = ((j < nc) ? b0 : bn) / yp[j];
        ws[j] = w;
    }
    __syncthreads();
    const int lane = tid & 31, wid = tid >> 5;
    float wsum = 0.f;
    for (int rr = 0; rr < 4; rr++) {
        int row = i0 + wid * 4 + rr;
        if (row > nt) break;
        const __half* Kp = g_Km + (size_t)g * CAP + (size_t)row * ld;
        const __half* Mp = g_Mh + (size_t)g * CAP + (size_t)row * ld;
        float acc = 0.f;
        for (int jb = lane * 8; jb < ld; jb += 256) {
            uint4 kv = *(const uint4*)(Kp + jb);
            uint4 mv = *(const uint4*)(Mp + jb);
            float4 w0 = *(const float4*)(ws + jb);
            float4 w1 = *(const float4*)(ws + jb + 4);
            const __half2* h = (const __half2*)&kv;
            const __half2* mm = (const __half2*)&mv;
            float2 f, m2;
            f = __half22float2(h[0]); m2 = __half22float2(mm[0]);
            acc = fmaf(f.x * m2.x, w0.x, acc); acc = fmaf(f.y * m2.y, w0.y, acc);
            f = __half22float2(h[1]); m2 = __half22float2(mm[1]);
            acc = fmaf(f.x * m2.x, w0.z, acc); acc = fmaf(f.y * m2.y, w0.w, acc);
            f = __half22float2(h[2]); m2 = __half22float2(mm[2]);
            acc = fmaf(f.x * m2.x, w1.x, acc); acc = fmaf(f.y * m2.y, w1.y, acc);
            f = __half22float2(h[3]); m2 = __half22float2(mm[3]);
            acc = fmaf(f.x * m2.x, w1.z, acc); acc = fmaf(f.y * m2.y, w1.w, acc);
        }
        #pragma unroll
        for (int o = 16; o; o >>= 1) acc += __shfl_down_sync(~0u, acc, o);
        if (!lane) wsum += g_z[g * VLD + row] * acc;    // g_z holds u
    }
    if (!lane) wp[wid] = wsum;
    __syncthreads();
    if (!tid) {
        float t2 = 0.f;
        #pragma unroll
        for (int w = 0; w < 8; w++) t2 += wp[w];
        g_cpart[s * 129 + bx] = t2;
    }
}

// ---------------- final deterministic sum -> d_out ----------------
__global__ void final_k(float* __restrict__ out) {
    __shared__ float ss[256];
    const int tid = threadIdx.x;
    float a = 0.f;
    for (int k = tid; k < SMAX * 129; k += 256) a += g_cpart[k];
    ss[tid] = a;
    __syncthreads();
    for (int o = 128; o; o >>= 1) { if (tid < o) ss[tid] += ss[tid + o]; __syncthreads(); }
    if (!tid) out[0] = 2.0f * ss[0];
}

extern "C" void kernel_launch(void* const* d_in, const int* in_sizes, int n_in,
                              void* d_out, int out_size) {
    (void)in_sizes; (void)n_in; (void)out_size;
    const float* X = (const float*)d_in[0];
    const int*   t = (const int*)d_in[1];

    partition_k<<<1, 256>>>(t);
    gather_k<<<(SMAX * NMAX * DDIM) / 256, 256>>>(X);
    norms_k<<<(SMAX * NMAX) / 8, 256>>>();

    gemm_k<<<dim3(32, 32, SMAX), 256>>>();
    reduce_k<<<SMAX, 256>>>();
    kbuild_k<<<dim3(NMAX + 1, SMAX), 256>>>();
    spmvA_k<<<dim3(33, SMAX), 256>>>();      // y0 = K^T a
    fused_k<<<FNB, 1024>>>();                // 20 fused iterations
    contract_k<<<dim3(129, SMAX), 256>>>();
    final_k<<<1, 256>>>((float*)d_out);
}